// round 9
// baseline (speedup 1.0000x reference)
#include <cuda_runtime.h>
#include <cuda_bf16.h>
#include <cstdint>

// Per-edge dot product: score[e] = dot(h[src[e]], h[dst[e]]), D=64.
//
// 8-lanes-per-edge, 8 edges per warp (2 passes of 4), Blackwell LDG.256:
//  - lane sub (0..7) of group grp loads the 32B chunk #sub of each 256B row
//    via ld.global.nc.v8.f32 -> ONE warp instruction gathers 4 full rows
//    (one per group) = 0.5 gather instructions per edge (vs 1 in R7).
//  - wavefronts/edge unchanged (4 line-touches), regs/edge unchanged.
//  - 3-stage butterfly within each 8-lane group (4 edges per SHFL instr).

#define ROWF 64  // floats per row

struct f8 { float v0, v1, v2, v3, v4, v5, v6, v7; };

__device__ __forceinline__ f8 ldg256(const float* p) {
    f8 r;
    asm volatile("ld.global.nc.v8.f32 {%0,%1,%2,%3,%4,%5,%6,%7}, [%8];"
                 : "=f"(r.v0), "=f"(r.v1), "=f"(r.v2), "=f"(r.v3),
                   "=f"(r.v4), "=f"(r.v5), "=f"(r.v6), "=f"(r.v7)
                 : "l"(p));
    return r;
}

__device__ __forceinline__ float dot8(const f8& a, const f8& b) {
    float s0 = a.v0 * b.v0 + a.v1 * b.v1;
    float s1 = a.v2 * b.v2 + a.v3 * b.v3;
    float s2 = a.v4 * b.v4 + a.v5 * b.v5;
    float s3 = a.v6 * b.v6 + a.v7 * b.v7;
    return (s0 + s1) + (s2 + s3);
}

__global__ __launch_bounds__(256)
void u_dot_v_kernel(const float* __restrict__ h,
                    const int* __restrict__ src,
                    const int* __restrict__ dst,
                    float* __restrict__ out,
                    int n_edges)
{
    const int warp = threadIdx.x >> 5;
    const int lane = threadIdx.x & 31;
    const int grp  = lane >> 3;           // edge group within warp (0..3)
    const unsigned sub = lane & 7;        // lane within group
    const unsigned gmask = 0xFFu << (grp << 3);

    // 8 edges per warp: pass p handles edge e_base + p*4 + grp
    const int e_base = (blockIdx.x * 8 + warp) * 8;
    if (e_base >= n_edges) return;

    const int eA = e_base + grp;          // pass 0
    const int eB = e_base + 4 + grp;      // pass 1

    if (e_base + 7 < n_edges) {
        // ---- fast path ----
        const unsigned sA = (unsigned)src[eA];
        const unsigned dA = (unsigned)dst[eA];
        const unsigned sB = (unsigned)src[eB];
        const unsigned dB = (unsigned)dst[eB];

        const float* pa = h + (size_t)sA * ROWF + sub * 8;
        const float* pb = h + (size_t)dA * ROWF + sub * 8;
        const float* pc = h + (size_t)sB * ROWF + sub * 8;
        const float* pd = h + (size_t)dB * ROWF + sub * 8;

        // 4 LDG.256 in flight: each fetches 4 complete rows across the warp
        const f8 a = ldg256(pa);
        const f8 b = ldg256(pb);
        const f8 c = ldg256(pc);
        const f8 d = ldg256(pd);

        float vA = dot8(a, b);
        float vB = dot8(c, d);

        // 3-stage butterfly within each 8-lane group (4 edges per instr)
        vA += __shfl_xor_sync(gmask, vA, 4);
        vB += __shfl_xor_sync(gmask, vB, 4);
        vA += __shfl_xor_sync(gmask, vA, 2);
        vB += __shfl_xor_sync(gmask, vB, 2);
        vA += __shfl_xor_sync(gmask, vA, 1);
        vB += __shfl_xor_sync(gmask, vB, 1);

        if (sub == 0) {
            out[eA] = vA;
            out[eB] = vB;
        }
    } else {
        // ---- tail path: clamp indices, guard stores ----
        const int nm1 = n_edges - 1;
        const int eAc = eA <= nm1 ? eA : nm1;
        const int eBc = eB <= nm1 ? eB : nm1;

        const unsigned sA = (unsigned)src[eAc];
        const unsigned dA = (unsigned)dst[eAc];
        const unsigned sB = (unsigned)src[eBc];
        const unsigned dB = (unsigned)dst[eBc];

        const f8 a = ldg256(h + (size_t)sA * ROWF + sub * 8);
        const f8 b = ldg256(h + (size_t)dA * ROWF + sub * 8);
        const f8 c = ldg256(h + (size_t)sB * ROWF + sub * 8);
        const f8 d = ldg256(h + (size_t)dB * ROWF + sub * 8);

        float vA = dot8(a, b);
        float vB = dot8(c, d);

        vA += __shfl_xor_sync(gmask, vA, 4);
        vB += __shfl_xor_sync(gmask, vB, 4);
        vA += __shfl_xor_sync(gmask, vA, 2);
        vB += __shfl_xor_sync(gmask, vB, 2);
        vA += __shfl_xor_sync(gmask, vA, 1);
        vB += __shfl_xor_sync(gmask, vB, 1);

        if (sub == 0) {
            if (eA < n_edges) out[eA] = vA;
            if (eB < n_edges) out[eB] = vB;
        }
    }
}

extern "C" void kernel_launch(void* const* d_in, const int* in_sizes, int n_in,
                              void* d_out, int out_size)
{
    const float* h   = (const float*)d_in[0];
    const int*   src = (const int*)d_in[1];
    const int*   dst = (const int*)d_in[2];
    float*       out = (float*)d_out;

    const int n_edges = in_sizes[1];
    const int edges_per_block = 8 * 8;   // 8 warps x 8 edges
    const int blocks = (n_edges + edges_per_block - 1) / edges_per_block;

    u_dot_v_kernel<<<blocks, 256>>>(h, src, dst, out, n_edges);
}